// round 13
// baseline (speedup 1.0000x reference)
#include <cuda_runtime.h>
#include <math_constants.h>

// Per-(batch, slice) x 4 grid-column partials: g_part[bid*4 + gc].
// bid = batch*16 + slice, slice = gr*4 + sub. Zero-init at module load.
__device__ float g_part[2048 * 4];
__device__ unsigned int g_done = 0;   // ticket; reset by last block each run

// ---------------------------------------------------------------------------
// Fused kernel: 2048 blocks x 256 threads, one block per 32-row SLICE
// (64 KB fully CONTIGUOUS — max DRAM row-buffer locality; the per-cell
// column split of R3-R12 produced 512B/2KB strided streams, DRAM stuck
// at 60-68%).
//
// Thread t: f4 = t&127 spans the full 512-float row; r0 = t>>7 row parity,
// rows r0+2i (i<16). Warp w<4 -> grid column gc=w (even rows); warp w>=4 ->
// gc=w-4 (odd rows). So ws[w]+ws[w+4] = block's partial for column w.
//
// Phase 2 (last block via threadfence ticket): thread b<128 sums the 4
// sub-partials per cell, 3x3 window sums, first-occurrence argmax, writes
// float (row, col). Mean /16384 skipped: uniform positive, argmax-safe.
// ---------------------------------------------------------------------------
__global__ __launch_bounds__(256) void region_selector_fused(
    const float* __restrict__ x, float* __restrict__ out)
{
    const int bid   = blockIdx.x;      // batch*16 + slice
    const int batch = bid >> 4;
    const int slice = bid & 15;        // gr = slice>>2, sub = slice&3

    const int t  = threadIdx.x;        // 0..255
    const int f4 = t & 127;            // float4 index within a 512-float row
    const int r0 = t >> 7;             // 0 or 1

    const float4* __restrict__ p = reinterpret_cast<const float4*>(x)
        + (size_t)batch * 65536 + (size_t)slice * 4096;   // slice base (f4)

    float s = 0.0f;
    #pragma unroll
    for (int i = 0; i < 16; i++) {
        const float4 v = __ldcs(&p[(r0 + 2 * i) * 128 + f4]);
        s += (v.x + v.y) + (v.z + v.w);
    }

    // Warp reduce: each warp lies within one (gc, parity).
    #pragma unroll
    for (int o = 16; o > 0; o >>= 1)
        s += __shfl_xor_sync(0xffffffffu, s, o);

    __shared__ float ws[8];
    __shared__ bool  is_last;
    if ((t & 31) == 0) ws[t >> 5] = s;
    __syncthreads();

    if (t < 4) {
        // gc = t: even-row partial ws[t] + odd-row partial ws[t+4].
        g_part[bid * 4 + t] = ws[t] + ws[t + 4];
    }
    __syncthreads();                   // ensure g_part writes issued pre-fence

    if (t == 0) {
        __threadfence();               // publish before ticket bump
        const unsigned int ticket = atomicAdd(&g_done, 1u);
        is_last = (ticket == gridDim.x - 1);
    }
    __syncthreads();

    if (is_last) {
        if (t < 128) {
            const int b = t;           // one batch per thread
            float cells[16];
            #pragma unroll
            for (int gr = 0; gr < 4; gr++)
                #pragma unroll
                for (int gc = 0; gc < 4; gc++) {
                    float c = 0.0f;
                    #pragma unroll
                    for (int sub = 0; sub < 4; sub++)
                        c += g_part[((b * 16 + gr * 4 + sub) << 2) + gc];
                    cells[gr * 4 + gc] = c;
                }

            float best = -CUDART_INF_F;
            int   bi   = 0;
            #pragma unroll
            for (int r = 0; r < 2; r++) {
                #pragma unroll
                for (int c = 0; c < 2; c++) {
                    float w = 0.0f;
                    #pragma unroll
                    for (int dr = 0; dr < 3; dr++)
                        #pragma unroll
                        for (int dc = 0; dc < 3; dc++)
                            w += cells[(r + dr) * 4 + (c + dc)];
                    if (w > best) { best = w; bi = r * 2 + c; }  // first-hit
                }
            }
            out[b * 2 + 0] = (float)(bi >> 1);  // row (float output dtype)
            out[b * 2 + 1] = (float)(bi & 1);   // col
        }
        if (t == 0) g_done = 0;        // reset for next graph replay
    }
}

extern "C" void kernel_launch(void* const* d_in, const int* in_sizes, int n_in,
                              void* d_out, int out_size) {
    const float* x = (const float*)d_in[0];
    float* out = (float*)d_out;
    region_selector_fused<<<2048, 256>>>(x, out);
}

// round 14
// speedup vs baseline: 1.1735x; 1.1735x over previous
#include <cuda_runtime.h>
#include <math_constants.h>

// One float per (batch, grid cell): index == blockIdx.x of kernel 1.
__device__ float g_cells[128 * 4 * 4];

// ---------------------------------------------------------------------------
// Kernel 1: one block per grid cell (best-measured phase-1 shape, R9/R10).
// 2048 blocks x 256 threads, 8 blocks/SM, 13.8 waves. __ldcs: evict-first
// won its controlled A/B (R10 25.6us vs R11 28.8us).
// Each block privately sums its 128x128 cell; thread t: c4 = t&31 (float4
// col), r0 = t>>5, rows r0+8i -> 16 independent coalesced loads (MLP 16).
// Per-block PDL trigger lets the dependent select kernel spin up early.
// ---------------------------------------------------------------------------
__global__ __launch_bounds__(256) void cell_reduce_kernel(const float* __restrict__ x) {
    const int bid   = blockIdx.x;      // batch*16 + gr*4 + gc
    const int batch = bid >> 4;
    const int cell  = bid & 15;
    const int gr    = cell >> 2;
    const int gc    = cell & 3;

    const int t  = threadIdx.x;        // 0..255
    const int c4 = t & 31;
    const int r0 = t >> 5;             // 0..7

    const float4* __restrict__ p =
        reinterpret_cast<const float4*>(x) + (size_t)batch * 65536;
    const int cellbase = gr * (128 * 128) + gc * 32;   // float4 units

    float s = 0.0f;
    #pragma unroll
    for (int i = 0; i < 16; i++) {
        const float4 v = __ldcs(&p[cellbase + (r0 + 8 * i) * 128 + c4]);
        s += (v.x + v.y) + (v.z + v.w);
    }

    #pragma unroll
    for (int o = 16; o > 0; o >>= 1)
        s += __shfl_xor_sync(0xffffffffu, s, o);

    __shared__ float ws[8];
    if ((t & 31) == 0) ws[t >> 5] = s;
    __syncthreads();

    if (t == 0) {
        g_cells[bid] = (ws[0] + ws[1]) + (ws[2] + ws[3])
                     + (ws[4] + ws[5]) + (ws[6] + ws[7]);
        __threadfence();               // publish before signaling completion
    }
    // PDL: signal this block's completion so the dependent kernel can start.
    cudaTriggerProgrammaticLaunchCompletion();
}

// ---------------------------------------------------------------------------
// Kernel 2 (PDL secondary): launches concurrently with kernel 1's tail;
// gridsync blocks until ALL kernel-1 blocks are done, then one thread per
// batch: 16 cell sums -> four 3x3 window sums -> first-occurrence argmax ->
// float (row, col). Mean /16384 skipped: uniform positive, argmax-safe.
// ---------------------------------------------------------------------------
__global__ __launch_bounds__(128) void select_kernel(float* __restrict__ out) {
    cudaGridDependencySynchronize();   // wait for kernel 1 to fully drain

    const int b = threadIdx.x;         // one batch per thread (grid = 1x128)
    float cells[16];
    #pragma unroll
    for (int i = 0; i < 16; i++) cells[i] = g_cells[b * 16 + i];

    float best = -CUDART_INF_F;
    int   bi   = 0;
    #pragma unroll
    for (int r = 0; r < 2; r++) {
        #pragma unroll
        for (int c = 0; c < 2; c++) {
            float w = 0.0f;
            #pragma unroll
            for (int dr = 0; dr < 3; dr++)
                #pragma unroll
                for (int dc = 0; dc < 3; dc++)
                    w += cells[(r + dr) * 4 + (c + dc)];
            if (w > best) { best = w; bi = r * 2 + c; }  // first-occurrence
        }
    }
    out[b * 2 + 0] = (float)(bi >> 1);  // row (float output dtype)
    out[b * 2 + 1] = (float)(bi & 1);   // col
}

extern "C" void kernel_launch(void* const* d_in, const int* in_sizes, int n_in,
                              void* d_out, int out_size) {
    const float* x = (const float*)d_in[0];
    float* out = (float*)d_out;

    cell_reduce_kernel<<<2048, 256>>>(x);

    // Launch select with Programmatic Stream Serialization: it may begin
    // while kernel 1 is still running; the gridsync inside provides the
    // real dependency. Graph capture preserves this as a programmatic edge.
    cudaLaunchConfig_t cfg = {};
    cfg.gridDim  = dim3(1, 1, 1);
    cfg.blockDim = dim3(128, 1, 1);
    cudaLaunchAttribute attr[1];
    attr[0].id = cudaLaunchAttributeProgrammaticStreamSerialization;
    attr[0].val.programmaticStreamSerializationAllowed = 1;
    cfg.attrs    = attr;
    cfg.numAttrs = 1;
    cudaLaunchKernelEx(&cfg, select_kernel, out);
}